// round 1
// baseline (speedup 1.0000x reference)
#include <cuda_runtime.h>

#define NB 4
#define NN 8192
#define NF 64
#define BM 128
#define BK 16
#define BN 64
#define APAD 4

// Scratch for the inter-layer activation [B, N, F] (8 MB). Device global:
// allocation-free per harness rules.
__device__ float g_mid[NB * NN * NF];

// One fused GCN layer: Zout[b,m,g] = relu( sum_f (sum_n A[m,n]*Zin[b,n,f]) * W[f,g] )
// Grid: (NN/BM, NB). Block: 256 threads, 8x4 register tile over a 128x64 output tile.
__global__ __launch_bounds__(256, 2)
void gcn_layer(const float* __restrict__ A,
               const float* __restrict__ Zin,
               const float* __restrict__ Wg,
               float* __restrict__ Zout)
{
    __shared__ float As[BK][BM + APAD];   // A tile, transposed (k-major)
    __shared__ float Zs[BK][BN];          // Z tile
    __shared__ float Ws[NF * NF];         // W[f][g], row-major
    __shared__ float Hs[64][BN + 1];      // half of the H tile for the W-epilogue

    const int tid = threadIdx.x;
    const int tx  = tid & 15;   // 0..15  -> 4 output cols each
    const int ty  = tid >> 4;   // 0..15  -> 8 output rows each
    const int m0  = blockIdx.x * BM;
    const int b   = blockIdx.y;

    const float* Zb = Zin + (size_t)b * NN * NF;

    // Load W (64x64 = 4096 floats): 4 float4 per thread.
    #pragma unroll
    for (int i = 0; i < 4; i++) {
        int idx = (tid + i * 256) * 4;
        *(float4*)&Ws[idx] = *(const float4*)&Wg[idx];
    }

    float acc[8][4];
    #pragma unroll
    for (int i = 0; i < 8; i++)
        #pragma unroll
        for (int j = 0; j < 4; j++)
            acc[i][j] = 0.0f;

    for (int k0 = 0; k0 < NN; k0 += BK) {
        // A tile: 128x16 floats = 512 float4, 2 per thread, stored transposed.
        #pragma unroll
        for (int v = 0; v < 2; v++) {
            int vid = tid + v * 256;
            int row = vid >> 2;          // 0..127
            int cv  = (vid & 3) * 4;     // 0,4,8,12
            float4 a = *(const float4*)&A[(size_t)(m0 + row) * NN + k0 + cv];
            As[cv + 0][row] = a.x;
            As[cv + 1][row] = a.y;
            As[cv + 2][row] = a.z;
            As[cv + 3][row] = a.w;
        }
        // Z tile: 16x64 floats = 256 float4, 1 per thread.
        {
            int row = tid >> 4;          // 0..15
            int cv  = (tid & 15) * 4;    // 0..60
            *(float4*)&Zs[row][cv] =
                *(const float4*)&Zb[(size_t)(k0 + row) * NF + cv];
        }
        __syncthreads();

        #pragma unroll
        for (int kk = 0; kk < BK; kk++) {
            float4 zv = *(float4*)&Zs[kk][tx * 4];
            float zf[4] = {zv.x, zv.y, zv.z, zv.w};
            #pragma unroll
            for (int i = 0; i < 8; i++) {
                float a = As[kk][ty * 8 + i];
                #pragma unroll
                for (int j = 0; j < 4; j++)
                    acc[i][j] = fmaf(a, zf[j], acc[i][j]);
            }
        }
        __syncthreads();
    }

    // Epilogue: Zout = relu(H @ W), processed in two 64-row halves so Hs fits
    // within the 48 KB static smem budget alongside As/Zs/Ws.
    float* outb = Zout + (size_t)b * NN * NF;
    #pragma unroll
    for (int h = 0; h < 2; h++) {
        // Owners of rows [64h, 64h+64) write their accumulators to Hs.
        if ((ty >> 3) == h) {
            int rbase = (ty & 7) * 8;
            #pragma unroll
            for (int i = 0; i < 8; i++)
                #pragma unroll
                for (int j = 0; j < 4; j++)
                    Hs[rbase + i][tx * 4 + j] = acc[i][j];
        }
        __syncthreads();

        // All 256 threads compute the 64x64 output block: 4 rows x 4 cols each.
        float o[4][4];
        #pragma unroll
        for (int ii = 0; ii < 4; ii++)
            #pragma unroll
            for (int j = 0; j < 4; j++)
                o[ii][j] = 0.0f;

        #pragma unroll
        for (int f = 0; f < NF; f++) {
            float4 wv = *(float4*)&Ws[f * NF + tx * 4];
            #pragma unroll
            for (int ii = 0; ii < 4; ii++) {
                float hv = Hs[ty * 4 + ii][f];
                o[ii][0] = fmaf(hv, wv.x, o[ii][0]);
                o[ii][1] = fmaf(hv, wv.y, o[ii][1]);
                o[ii][2] = fmaf(hv, wv.z, o[ii][2]);
                o[ii][3] = fmaf(hv, wv.w, o[ii][3]);
            }
        }

        #pragma unroll
        for (int ii = 0; ii < 4; ii++) {
            int m = h * 64 + ty * 4 + ii;
            float4 r;
            r.x = fmaxf(o[ii][0], 0.0f);
            r.y = fmaxf(o[ii][1], 0.0f);
            r.z = fmaxf(o[ii][2], 0.0f);
            r.w = fmaxf(o[ii][3], 0.0f);
            *(float4*)&outb[(size_t)(m0 + m) * NF + tx * 4] = r;
        }
        __syncthreads();  // Hs reused by next half
    }
}

extern "C" void kernel_launch(void* const* d_in, const int* in_sizes, int n_in,
                              void* d_out, int out_size)
{
    // Identify inputs by element count (robust to metadata ordering):
    //   x: 4*8192*64 = 2097152, t: 1, net_params: 2*64*64 = 8192, A: 8192*8192 = 67108864
    const float* x   = nullptr;
    const float* net = nullptr;
    const float* A   = nullptr;
    for (int i = 0; i < n_in; i++) {
        if (in_sizes[i] == NB * NN * NF)      x   = (const float*)d_in[i];
        else if (in_sizes[i] == 2 * NF * NF)  net = (const float*)d_in[i];
        else if (in_sizes[i] == NN * NN)      A   = (const float*)d_in[i];
    }
    float* out = (float*)d_out;

    float* mid = nullptr;
    cudaGetSymbolAddress((void**)&mid, g_mid);

    dim3 grid(NN / BM, NB);
    dim3 block(256);
    // Layer 0: x -> mid
    gcn_layer<<<grid, block>>>(A, x, net, mid);
    // Layer 1: mid -> out
    gcn_layer<<<grid, block>>>(A, mid, net + NF * NF, out);
}

// round 4
// speedup vs baseline: 1.9364x; 1.9364x over previous
#include <cuda_runtime.h>
#include <cuda_bf16.h>
#include <cstdint>

#define NB 4
#define NN 8192
#define NF 64
#define BM 128
#define BN 128
#define BK 32
#define NITER (NN / BK)   // 256
#define STAGES 3

// ---------------- device scratch (static; no allocs) ----------------
__device__ __nv_bfloat16 g_Ahi[67108864];
__device__ __nv_bfloat16 g_Alo[67108864];
__device__ __nv_bfloat16 g_zhi0[NB * NF * NN];
__device__ __nv_bfloat16 g_zlo0[NB * NF * NN];
__device__ __nv_bfloat16 g_zhi1[NB * NF * NN];
__device__ __nv_bfloat16 g_zlo1[NB * NF * NN];

// ---------------- smem layout ----------------
// Padded rows: 32 bf16 data + 8 pad = 40 bf16 = 80 B (conflict-free ldmatrix)
#define ROWB     80
#define BUF_SZ   (128 * ROWB)            // 10240 B per operand tile
#define STAGE_SZ (4 * BUF_SZ)            // Ahi,Alo,Bhi,Blo = 40960 B
#define WS_OFF   (STAGES * STAGE_SZ)     // 122880
#define SMEM_TOTAL (WS_OFF + NF * NF * 4)  // 139264
#define HS_STRIDE 132                    // fp32 H tile stride (epilogue, reuses stages)

__device__ __forceinline__ uint32_t smem_u32(const void* p) {
    uint32_t a;
    asm("{ .reg .u64 t; cvta.to.shared.u64 t, %1; cvt.u32.u64 %0, t; }"
        : "=r"(a) : "l"(p));
    return a;
}
__device__ __forceinline__ void cp16(uint32_t dst, const void* src) {
    asm volatile("cp.async.cg.shared.global [%0], [%1], 16;" :: "r"(dst), "l"(src));
}
#define CP_COMMIT() asm volatile("cp.async.commit_group;" ::: "memory")
#define CP_WAIT(n)  asm volatile("cp.async.wait_group %0;" :: "n"(n) : "memory")

#define LDSM_X4(r0, r1, r2, r3, a) \
    asm volatile("ldmatrix.sync.aligned.m8n8.x4.shared.b16 {%0,%1,%2,%3}, [%4];" \
                 : "=r"(r0), "=r"(r1), "=r"(r2), "=r"(r3) : "r"(a))
#define LDSM_X2(r0, r1, a) \
    asm volatile("ldmatrix.sync.aligned.m8n8.x2.shared.b16 {%0,%1}, [%2];" \
                 : "=r"(r0), "=r"(r1) : "r"(a))
#define MMA_BF16(c, a, b) \
    asm volatile("mma.sync.aligned.m16n8k16.row.col.f32.bf16.bf16.f32 " \
                 "{%0,%1,%2,%3}, {%4,%5,%6,%7}, {%8,%9}, {%0,%1,%2,%3};" \
                 : "+f"((c)[0]), "+f"((c)[1]), "+f"((c)[2]), "+f"((c)[3]) \
                 : "r"((a)[0]), "r"((a)[1]), "r"((a)[2]), "r"((a)[3]), \
                   "r"((b)[0]), "r"((b)[1]))

// ================= split A: fp32 -> bf16 hi + lo =================
__global__ __launch_bounds__(256)
void split_A(const float* __restrict__ A,
             __nv_bfloat16* __restrict__ hi, __nv_bfloat16* __restrict__ lo)
{
    size_t i = ((size_t)blockIdx.x * 256 + threadIdx.x) * 8;
    float4 a0 = *(const float4*)&A[i];
    float4 a1 = *(const float4*)&A[i + 4];
    float v[8] = {a0.x, a0.y, a0.z, a0.w, a1.x, a1.y, a1.z, a1.w};
    unsigned short hs[8], ls[8];
    #pragma unroll
    for (int k = 0; k < 8; k++) {
        __nv_bfloat16 h = __float2bfloat16(v[k]);
        __nv_bfloat16 l = __float2bfloat16(v[k] - __bfloat162float(h));
        hs[k] = *(unsigned short*)&h;
        ls[k] = *(unsigned short*)&l;
    }
    *(uint4*)&hi[i] = *(uint4*)hs;
    *(uint4*)&lo[i] = *(uint4*)ls;
}

// ========= transpose+split x: x[b][n][f] -> z{hi,lo}[b*64+f][n] =========
__global__ __launch_bounds__(256)
void transpose_split_x(const float* __restrict__ x,
                       __nv_bfloat16* __restrict__ zhi,
                       __nv_bfloat16* __restrict__ zlo)
{
    __shared__ float tile[64][65];
    const int n0 = blockIdx.x * 64;
    const int b  = blockIdx.y;
    const int tid = threadIdx.x;

    #pragma unroll
    for (int v = 0; v < 4; v++) {
        int idx = tid + v * 256;
        int i = idx >> 4, f4 = (idx & 15) * 4;
        float4 a = *(const float4*)&x[((size_t)b * NN + n0 + i) * NF + f4];
        tile[i][f4 + 0] = a.x; tile[i][f4 + 1] = a.y;
        tile[i][f4 + 2] = a.z; tile[i][f4 + 3] = a.w;
    }
    __syncthreads();
    #pragma unroll
    for (int v = 0; v < 4; v++) {
        int idx = tid + v * 256;
        int f = idx >> 4, i4 = (idx & 15) * 4;
        unsigned short hs[4], ls[4];
        #pragma unroll
        for (int k = 0; k < 4; k++) {
            float val = tile[i4 + k][f];
            __nv_bfloat16 h = __float2bfloat16(val);
            __nv_bfloat16 l = __float2bfloat16(val - __bfloat162float(h));
            hs[k] = *(unsigned short*)&h;
            ls[k] = *(unsigned short*)&l;
        }
        size_t o = (size_t)(b * NF + f) * NN + n0 + i4;
        *(uint2*)&zhi[o] = *(uint2*)hs;
        *(uint2*)&zlo[o] = *(uint2*)ls;
    }
}

// ================= fused GCN layer: mma.sync bf16 3-term =================
__global__ __launch_bounds__(256, 1)
void gcn_mma(const __nv_bfloat16* __restrict__ Ahi,
             const __nv_bfloat16* __restrict__ Alo,
             const __nv_bfloat16* __restrict__ Bhi,
             const __nv_bfloat16* __restrict__ Blo,
             const float* __restrict__ Wg,
             float* __restrict__ out_f,
             __nv_bfloat16* __restrict__ out_hi,
             __nv_bfloat16* __restrict__ out_lo,
             int layer)
{
    extern __shared__ char smem[];
    const uint32_t sbase = smem_u32(smem);
    const int tid  = threadIdx.x;
    const int lane = tid & 31;
    const int wid  = tid >> 5;
    const int wm   = wid & 1;       // 0/1 -> 64-row half
    const int wn   = wid >> 1;      // 0..3 -> 32-col slice
    const int m0   = blockIdx.x * BM;
    const int n0   = blockIdx.y * BN;

    // W into smem
    float* Ws = (float*)(smem + WS_OFF);
    #pragma unroll
    for (int i = 0; i < 4; i++)
        ((float4*)Ws)[tid + i * 256] = ((const float4*)Wg)[tid + i * 256];

    float acc[4][4][4];
    #pragma unroll
    for (int mt = 0; mt < 4; mt++)
        #pragma unroll
        for (int nt = 0; nt < 4; nt++)
            #pragma unroll
            for (int r = 0; r < 4; r++)
                acc[mt][nt][r] = 0.0f;

    // per-thread load slice: row = tid>>1 (0..127), chunks (tid&1)*2 + {0,1}
    const int lrow = tid >> 1;
    const int lc0  = (tid & 1) * 2;

    auto load_tile = [&](int stage, int k0) {
        uint32_t ss = sbase + stage * STAGE_SZ;
        #pragma unroll
        for (int u = 0; u < 2; u++) {
            int c = lc0 + u;
            uint32_t d = ss + lrow * ROWB + c * 16;
            size_t ao = (size_t)(m0 + lrow) * NN + k0 + c * 8;
            size_t bo = (size_t)(n0 + lrow) * NN + k0 + c * 8;
            cp16(d,              Ahi + ao);
            cp16(d + BUF_SZ,     Alo + ao);
            cp16(d + 2 * BUF_SZ, Bhi + bo);
            cp16(d + 3 * BUF_SZ, Blo + bo);
        }
        CP_COMMIT();
    };

    load_tile(0, 0);
    load_tile(1, BK);

    // ldmatrix per-thread base offsets
    const uint32_t a_off = (uint32_t)(wm * 64 + (lane & 15)) * ROWB + (lane >> 4) * 16;
    const uint32_t b_off = (uint32_t)(wn * 32 + (lane & 7))  * ROWB + ((lane >> 3) & 1) * 16;

    for (int j = 0; j < NITER; j++) {
        if (j < NITER - 1) CP_WAIT(1); else CP_WAIT(0);
        __syncthreads();
        if (j + 2 < NITER) load_tile((j + 2) % STAGES, (j + 2) * BK);

        uint32_t ss  = sbase + (j % STAGES) * STAGE_SZ;
        uint32_t ah_base = ss + a_off;
        uint32_t bh_base = ss + 2 * BUF_SZ + b_off;

        #pragma unroll
        for (int ks = 0; ks < 2; ks++) {
            uint32_t ah[4][4], al[4][4], bh[4][2], bl[4][2];
            #pragma unroll
            for (int mt = 0; mt < 4; mt++) {
                uint32_t a = ah_base + mt * (16 * ROWB) + ks * 32;
                LDSM_X4(ah[mt][0], ah[mt][1], ah[mt][2], ah[mt][3], a);
                LDSM_X4(al[mt][0], al[mt][1], al[mt][2], al[mt][3], a + BUF_SZ);
            }
            #pragma unroll
            for (int nt = 0; nt < 4; nt++) {
                uint32_t b = bh_base + nt * (8 * ROWB) + ks * 32;
                LDSM_X2(bh[nt][0], bh[nt][1], b);
                LDSM_X2(bl[nt][0], bl[nt][1], b + BUF_SZ);
            }
            #pragma unroll
            for (int mt = 0; mt < 4; mt++)
                #pragma unroll
                for (int nt = 0; nt < 4; nt++) {
                    MMA_BF16(acc[mt][nt], ah[mt], bh[nt]);
                    MMA_BF16(acc[mt][nt], ah[mt], bl[nt]);
                    MMA_BF16(acc[mt][nt], al[mt], bh[nt]);
                }
        }
    }

    // ---------------- epilogue: O = relu(H @ W) ----------------
    __syncthreads();                       // all smem reads done; reuse stages as Hs
    float* Hs = (float*)smem;              // [128][HS_STRIDE]
    const int lr = lane >> 2, lc = (lane & 3) * 2;
    #pragma unroll
    for (int mt = 0; mt < 4; mt++) {
        int m = wm * 64 + mt * 16 + lr;
        #pragma unroll
        for (int nt = 0; nt < 4; nt++) {
            int c = wn * 32 + nt * 8 + lc;
            Hs[m * HS_STRIDE + c]           = acc[mt][nt][0];
            Hs[m * HS_STRIDE + c + 1]       = acc[mt][nt][1];
            Hs[(m + 8) * HS_STRIDE + c]     = acc[mt][nt][2];
            Hs[(m + 8) * HS_STRIDE + c + 1] = acc[mt][nt][3];
        }
    }
    __syncthreads();

    const int ty = tid >> 4;            // 0..15 -> 8 rows each
    const int tx = tid & 15;
    const int lb = tx >> 3;             // local batch 0/1
    const int g0 = (tx & 7) * 8;
    const int b  = blockIdx.y * 2 + lb;

    float o[8][8];
    #pragma unroll
    for (int i = 0; i < 8; i++)
        #pragma unroll
        for (int g = 0; g < 8; g++)
            o[i][g] = 0.0f;

    #pragma unroll 4
    for (int f = 0; f < NF; f++) {
        float4 w0 = *(const float4*)&Ws[f * NF + g0];
        float4 w1 = *(const float4*)&Ws[f * NF + g0 + 4];
        #pragma unroll
        for (int i = 0; i < 8; i++) {
            float hv = Hs[(ty * 8 + i) * HS_STRIDE + lb * 64 + f];
            o[i][0] = fmaf(hv, w0.x, o[i][0]);
            o[i][1] = fmaf(hv, w0.y, o[i][1]);
            o[i][2] = fmaf(hv, w0.z, o[i][2]);
            o[i][3] = fmaf(hv, w0.w, o[i][3]);
            o[i][4] = fmaf(hv, w1.x, o[i][4]);
            o[i][5] = fmaf(hv, w1.y, o[i][5]);
            o[i][6] = fmaf(hv, w1.z, o[i][6]);
            o[i][7] = fmaf(hv, w1.w, o[i][7]);
        }
    }

    if (layer == 0) {
        #pragma unroll
        for (int i = 0; i < 8; i++) {
            int n = m0 + ty * 8 + i;
            #pragma unroll
            for (int g = 0; g < 8; g++) {
                float v = fmaxf(o[i][g], 0.0f);
                __nv_bfloat16 h = __float2bfloat16(v);
                __nv_bfloat16 l = __float2bfloat16(v - __bfloat162float(h));
                size_t off = (size_t)(b * NF + g0 + g) * NN + n;
                out_hi[off] = h;
                out_lo[off] = l;
            }
        }
    } else {
        #pragma unroll
        for (int i = 0; i < 8; i++) {
            int n = m0 + ty * 8 + i;
            float4 r0, r1;
            r0.x = fmaxf(o[i][0], 0.0f); r0.y = fmaxf(o[i][1], 0.0f);
            r0.z = fmaxf(o[i][2], 0.0f); r0.w = fmaxf(o[i][3], 0.0f);
            r1.x = fmaxf(o[i][4], 0.0f); r1.y = fmaxf(o[i][5], 0.0f);
            r1.z = fmaxf(o[i][6], 0.0f); r1.w = fmaxf(o[i][7], 0.0f);
            float* dst = &out_f[((size_t)b * NN + n) * NF + g0];
            *(float4*)dst       = r0;
            *(float4*)(dst + 4) = r1;
        }
    }
}

extern "C" void kernel_launch(void* const* d_in, const int* in_sizes, int n_in,
                              void* d_out, int out_size)
{
    const float* x   = nullptr;
    const float* net = nullptr;
    const float* A   = nullptr;
    for (int i = 0; i < n_in; i++) {
        if (in_sizes[i] == NB * NN * NF)      x   = (const float*)d_in[i];
        else if (in_sizes[i] == 2 * NF * NF)  net = (const float*)d_in[i];
        else if (in_sizes[i] == NN * NN)      A   = (const float*)d_in[i];
    }
    float* out = (float*)d_out;

    __nv_bfloat16 *Ahi, *Alo, *zhi0, *zlo0, *zhi1, *zlo1;
    cudaGetSymbolAddress((void**)&Ahi,  g_Ahi);
    cudaGetSymbolAddress((void**)&Alo,  g_Alo);
    cudaGetSymbolAddress((void**)&zhi0, g_zhi0);
    cudaGetSymbolAddress((void**)&zlo0, g_zlo0);
    cudaGetSymbolAddress((void**)&zhi1, g_zhi1);
    cudaGetSymbolAddress((void**)&zlo1, g_zlo1);

    cudaFuncSetAttribute(gcn_mma, cudaFuncAttributeMaxDynamicSharedMemorySize,
                         SMEM_TOTAL);

    split_A<<<32768, 256>>>(A, Ahi, Alo);
    transpose_split_x<<<dim3(NN / 64, NB), 256>>>(x, zhi0, zlo0);

    dim3 grid(NN / BM, 2);
    gcn_mma<<<grid, 256, SMEM_TOTAL>>>(Ahi, Alo, zhi0, zlo0, net,
                                       nullptr, zhi1, zlo1, 0);
    gcn_mma<<<grid, 256, SMEM_TOTAL>>>(Ahi, Alo, zhi1, zlo1, net + NF * NF,
                                       out, nullptr, nullptr, 1);
}